// round 11
// baseline (speedup 1.0000x reference)
#include <cuda_runtime.h>
#include <cuda_bf16.h>
#include <math.h>
#include <stdint.h>

#define NN 100000
#define NE 1600000
#define NB 98  // ceil(NN/1024) scan blocks

// ---------------- scratch (static __device__, no allocation) ----------------
__device__ __align__(16) float g_agg1[(size_t)NN * 128]; // layer-1 neighbor means
__device__ __align__(16) float g_tr[(size_t)NN * 80];    // [h@W2l | h@W2r] per node
// weights pre-transposed to [N][K] (K contiguous) and split into bf16 hi/lo
__device__ __align__(16) unsigned short g_w1h[128 * 256];
__device__ __align__(16) unsigned short g_w1lo[128 * 256];
__device__ __align__(16) unsigned short g_w2h[80 * 128];
__device__ __align__(16) unsigned short g_w2lo[80 * 128];
__device__ int g_src[NE];
__device__ int g_dst[NE];
__device__ int g_csr[NE];
__device__ int g_deg[NN];
__device__ int g_rowstart[NN];
__device__ int g_cursor[NN];
__device__ int g_scan[NN];
__device__ int g_bsum[NB];
__device__ int g_is64;

// ---------------- PTX helpers (sm_80-era, valid at compute_100) ----------------
static __device__ __forceinline__ uint32_t s2u(const void* p) {
    uint32_t a;
    asm("{ .reg .u64 t; cvta.to.shared.u64 t, %1; cvt.u32.u64 %0, t; }" : "=r"(a) : "l"(p));
    return a;
}
#define LDMX4(r0, r1, r2, r3, addr)                                             \
    asm volatile("ldmatrix.sync.aligned.m8n8.x4.shared.b16 {%0,%1,%2,%3}, [%4];" \
                 : "=r"(r0), "=r"(r1), "=r"(r2), "=r"(r3) : "r"(addr))
#define MMA16816(d, a0, a1, a2, a3, b0, b1)                                     \
    asm volatile("mma.sync.aligned.m16n8k16.row.col.f32.bf16.bf16.f32 "          \
                 "{%0,%1,%2,%3},{%4,%5,%6,%7},{%8,%9},{%0,%1,%2,%3};"            \
                 : "+f"((d)[0]), "+f"((d)[1]), "+f"((d)[2]), "+f"((d)[3])        \
                 : "r"(a0), "r"(a1), "r"(a2), "r"(a3), "r"(b0), "r"(b1))

// split fp32 pair -> packed bf16x2 hi (trunc) + lo (rn residual)
static __device__ __forceinline__ void pack_hilo(float x, float y,
                                                 uint32_t& h, uint32_t& l) {
    uint32_t ux = __float_as_uint(x), uy = __float_as_uint(y);
    h = (ux >> 16) | (uy & 0xFFFF0000u);
    unsigned short lx = __bfloat16_as_ushort(
        __float2bfloat16(x - __uint_as_float(ux & 0xFFFF0000u)));
    unsigned short ly = __bfloat16_as_ushort(
        __float2bfloat16(y - __uint_as_float(uy & 0xFFFF0000u)));
    l = (uint32_t)lx | ((uint32_t)ly << 16);
}

// ---------------- probe edge_index dtype (one warp, parallel) ----------------
__global__ void probe_k(const int* __restrict__ ei32) {
    int lane = threadIdx.x;
    int bad = 0;
#pragma unroll
    for (int i = 0; i < 4; i++)
        if (ei32[2 * (lane + 32 * i) + 1] != 0) bad = 1;
    bad = __any_sync(0xffffffffu, bad);
    if (lane == 0) g_is64 = bad ? 0 : 1;
}

// ---------------- setup: zero int scratch + pack/split weights ----------------
static __device__ __forceinline__ void split1(float v, unsigned short& h, unsigned short& l) {
    uint32_t u = __float_as_uint(v);
    h = (unsigned short)(u >> 16);
    float hf = __uint_as_float(u & 0xFFFF0000u);
    l = __bfloat16_as_ushort(__float2bfloat16(v - hf));
}
__global__ void setup_k(const float* __restrict__ W1l, const float* __restrict__ W1r,
                        const float* __restrict__ W2l, const float* __restrict__ W2r) {
    int i = blockIdx.x * blockDim.x + threadIdx.x;
    if (i < NN) { g_deg[i] = 0; g_cursor[i] = 0; }
    if (i < 128 * 256) { // w1: n = i/256, k = i%256
        int n = i >> 8, k = i & 255;
        float v = (k < 128) ? W1l[k * 128 + n] : W1r[(k - 128) * 128 + n];
        split1(v, g_w1h[i], g_w1lo[i]);
    }
    if (i < 80 * 128) { // w2: n = i/128, k = i%128
        int n = i >> 7, k = i & 127;
        float v = (n < 40) ? W2l[k * 40 + n] : W2r[k * 40 + (n - 40)];
        split1(v, g_w2h[i], g_w2lo[i]);
    }
}

// ---------------- edge convert + degree histogram ----------------
__global__ void convert_k(const void* __restrict__ ei) {
    int e = blockIdx.x * blockDim.x + threadIdx.x;
    if (e >= NE) return;
    int src, dst;
    if (g_is64) {
        src = (int)((const long long*)ei)[e];
        dst = (int)((const long long*)ei)[(long long)NE + e];
    } else {
        src = ((const int*)ei)[e];
        dst = ((const int*)ei)[NE + e];
    }
    g_src[e] = src;
    g_dst[e] = dst;
    atomicAdd(&g_deg[dst], 1);
}

// ---------------- prefix scan ----------------
__global__ __launch_bounds__(1024) void scan1_k() {
    __shared__ int s[1024];
    int t = threadIdx.x;
    int i = blockIdx.x * 1024 + t;
    int v = (i < NN) ? g_deg[i] : 0;
    s[t] = v;
    __syncthreads();
#pragma unroll
    for (int off = 1; off < 1024; off <<= 1) {
        int a = (t >= off) ? s[t - off] : 0;
        __syncthreads();
        s[t] += a;
        __syncthreads();
    }
    if (i < NN) g_scan[i] = s[t];
    if (t == 1023) g_bsum[blockIdx.x] = s[t];
}
__global__ void scan2_k() { // parallel Hillis-Steele over NB block sums
    __shared__ int s[128];
    int t = threadIdx.x;
    s[t] = (t < NB) ? g_bsum[t] : 0;
    __syncthreads();
#pragma unroll
    for (int off = 1; off < 128; off <<= 1) {
        int a = (t >= off) ? s[t - off] : 0;
        __syncthreads();
        s[t] += a;
        __syncthreads();
    }
    if (t < NB) g_bsum[t] = s[t];
}
__global__ void scan3_k() {
    int i = blockIdx.x * blockDim.x + threadIdx.x;
    if (i >= NN) return;
    int b = i >> 10;
    int base = (b > 0) ? g_bsum[b - 1] : 0;
    g_rowstart[i] = base + g_scan[i] - g_deg[i];
}

// ---------------- CSR fill ----------------
__global__ void fill_k() {
    int e = blockIdx.x * blockDim.x + threadIdx.x;
    if (e >= NE) return;
    int d = g_dst[e];
    int pos = g_rowstart[d] + atomicAdd(&g_cursor[d], 1);
    g_csr[pos] = g_src[e];
}

// ---------------- layer-1 gather-mean (unroll 4) ----------------
__global__ void agg1_k(const float* __restrict__ x) {
    int gt = blockIdx.x * blockDim.x + threadIdx.x;
    int n = gt >> 5;
    int lane = gt & 31;
    if (n >= NN) return;
    int start = g_rowstart[n];
    int deg = g_deg[n];
    float4 acc = make_float4(0.f, 0.f, 0.f, 0.f);
    int i = 0;
    for (; i + 3 < deg; i += 4) {
        int s0 = __ldg(g_csr + start + i);
        int s1 = __ldg(g_csr + start + i + 1);
        int s2 = __ldg(g_csr + start + i + 2);
        int s3 = __ldg(g_csr + start + i + 3);
        float4 v0 = ((const float4*)(x + (size_t)s0 * 128))[lane];
        float4 v1 = ((const float4*)(x + (size_t)s1 * 128))[lane];
        float4 v2 = ((const float4*)(x + (size_t)s2 * 128))[lane];
        float4 v3 = ((const float4*)(x + (size_t)s3 * 128))[lane];
        acc.x += (v0.x + v1.x) + (v2.x + v3.x);
        acc.y += (v0.y + v1.y) + (v2.y + v3.y);
        acc.z += (v0.z + v1.z) + (v2.z + v3.z);
        acc.w += (v0.w + v1.w) + (v2.w + v3.w);
    }
    for (; i < deg; i++) {
        int s0 = __ldg(g_csr + start + i);
        float4 v0 = ((const float4*)(x + (size_t)s0 * 128))[lane];
        acc.x += v0.x; acc.y += v0.y; acc.z += v0.z; acc.w += v0.w;
    }
    float inv = 1.0f / fmaxf((float)deg, 1.0f);
    acc.x *= inv; acc.y *= inv; acc.z *= inv; acc.w *= inv;
    ((float4*)(g_agg1 + (size_t)n * 128))[lane] = acc;
}

// ---------------- fused split-bf16 GEMM: tr = relu([agg|x]@W1 + b1) @ W2 ----------------
// Phase 1: acc1[128x128] = [A0|A1] @ W1 (3-MMA split-bf16), K=256 in 32-chunks.
// Bridge:  bias+relu in regs; D-fragments of acc1 repack directly as A-fragments.
// Phase 2: acc2[128x80] = h @ W2 (W2 hi/lo resident in SMEM), K=128.
__global__ __launch_bounds__(256) void gemm_fused(
    int M, const float* __restrict__ A0, const float* __restrict__ A1,
    const float* __restrict__ bias, float* __restrict__ C) {
    extern __shared__ unsigned short sm[];
    // offsets in ushorts
    unsigned short* sAh = sm;                 // 128*40
    unsigned short* sAl = sm + 5120;          // 128*40
    unsigned short* sBh = sm + 10240;         // 128*40
    unsigned short* sBl = sm + 15360;         // 128*40
    unsigned short* sW2h = sm + 20480;        // 80*136
    unsigned short* sW2l = sm + 31360;        // 80*136
    constexpr int ST = 40;    // chunk row stride (ushorts)
    constexpr int ST2 = 136;  // W2 row stride (ushorts)

    const int tid = threadIdx.x;
    const int wid = tid >> 5, lane = tid & 31;
    const int rowBase = blockIdx.x * 128;

    // ---- phase 0: W2 planes resident (uint4 = 8 ushorts -> 16 chunks/row) ----
    for (int idx = tid; idx < 1280; idx += 256) {
        int n = idx >> 4, q = idx & 15;
        *(uint4*)&sW2h[n * ST2 + q * 8] = *(const uint4*)(g_w2h + n * 128 + q * 8);
        *(uint4*)&sW2l[n * ST2 + q * 8] = *(const uint4*)(g_w2lo + n * 128 + q * 8);
    }

    float acc1[16][4];
#pragma unroll
    for (int t = 0; t < 16; t++)
#pragma unroll
        for (int q = 0; q < 4; q++) acc1[t][q] = 0.f;

    const int arow = tid >> 1;
    const int ach = (tid & 1) * 16;
    const int gr_a = rowBase + arow;

    // ---- phase 1: K=256 over 8 chunks of 32 ----
    for (int c = 0; c < 8; c++) {
        const int gk = c * 32;
        const float* Ap = (gk < 128) ? (A0 + (size_t)gr_a * 128 + gk + ach)
                                     : (A1 + (size_t)gr_a * 128 + (gk - 128) + ach);
#pragma unroll
        for (int i = 0; i < 4; i++) {
            float4 v = (gr_a < M) ? *(const float4*)(Ap + i * 4)
                                  : make_float4(0.f, 0.f, 0.f, 0.f);
            uint32_t h0, l0, h1, l1;
            pack_hilo(v.x, v.y, h0, l0);
            pack_hilo(v.z, v.w, h1, l1);
            *(uint2*)&sAh[arow * ST + ach + i * 4] = make_uint2(h0, h1);
            *(uint2*)&sAl[arow * ST + ach + i * 4] = make_uint2(l0, l1);
        }
        for (int idx = tid; idx < 128 * 4; idx += 256) {
            int n = idx >> 2, q = idx & 3;
            *(uint4*)&sBh[n * ST + q * 8] = *(const uint4*)(g_w1h + (size_t)n * 256 + gk + q * 8);
            *(uint4*)&sBl[n * ST + q * 8] = *(const uint4*)(g_w1lo + (size_t)n * 256 + gk + q * 8);
        }
        __syncthreads();
#pragma unroll
        for (int ks = 0; ks < 2; ks++) {
            const int kb = ks * 16;
            const int am = wid * 16 + (lane & 7) + ((lane >> 3) & 1) * 8;
            const int ak = kb + (lane >> 4) * 8;
            uint32_t ah0, ah1, ah2, ah3, al0, al1, al2, al3;
            {
                uint32_t addr = s2u(&sAh[am * ST + ak]);
                LDMX4(ah0, ah1, ah2, ah3, addr);
                addr = s2u(&sAl[am * ST + ak]);
                LDMX4(al0, al1, al2, al3, addr);
            }
            const int bn = (lane & 7) + (lane >> 4) * 8;
            const int bk = kb + ((lane >> 3) & 1) * 8;
#pragma unroll
            for (int p = 0; p < 8; p++) {
                uint32_t bh0, bh1, bh2, bh3, bl0_, bl1_, bl2_, bl3_;
                uint32_t addr = s2u(&sBh[(p * 16 + bn) * ST + bk]);
                LDMX4(bh0, bh1, bh2, bh3, addr);
                addr = s2u(&sBl[(p * 16 + bn) * ST + bk]);
                LDMX4(bl0_, bl1_, bl2_, bl3_, addr);
                MMA16816(acc1[2 * p + 0], ah0, ah1, ah2, ah3, bh0, bh1);
                MMA16816(acc1[2 * p + 0], ah0, ah1, ah2, ah3, bl0_, bl1_);
                MMA16816(acc1[2 * p + 0], al0, al1, al2, al3, bh0, bh1);
                MMA16816(acc1[2 * p + 1], ah0, ah1, ah2, ah3, bh2, bh3);
                MMA16816(acc1[2 * p + 1], ah0, ah1, ah2, ah3, bl2_, bl3_);
                MMA16816(acc1[2 * p + 1], al0, al1, al2, al3, bh2, bh3);
            }
        }
        __syncthreads();
    }

    // ---- bridge: bias + relu in registers ----
    const int cpair = (lane & 3) * 2;
#pragma unroll
    for (int t = 0; t < 16; t++) {
        int col = t * 8 + cpair;
        float b0v = __ldg(bias + col), b1v = __ldg(bias + col + 1);
        acc1[t][0] = fmaxf(acc1[t][0] + b0v, 0.f);
        acc1[t][1] = fmaxf(acc1[t][1] + b1v, 0.f);
        acc1[t][2] = fmaxf(acc1[t][2] + b0v, 0.f);
        acc1[t][3] = fmaxf(acc1[t][3] + b1v, 0.f);
    }

    // ---- phase 2: acc2 = h @ W2, h supplied from acc1 register fragments ----
    float acc2[10][4];
#pragma unroll
    for (int t = 0; t < 10; t++)
#pragma unroll
        for (int q = 0; q < 4; q++) acc2[t][q] = 0.f;

    const int bn2 = (lane & 7) + (lane >> 4) * 8;
    const int bkb = ((lane >> 3) & 1) * 8;
#pragma unroll
    for (int j = 0; j < 8; j++) {
        // A fragment for k-window [16j,16j+16) == acc1 tiles 2j, 2j+1
        uint32_t ah[4], al[4];
        pack_hilo(acc1[2 * j][0], acc1[2 * j][1], ah[0], al[0]);
        pack_hilo(acc1[2 * j][2], acc1[2 * j][3], ah[1], al[1]);
        pack_hilo(acc1[2 * j + 1][0], acc1[2 * j + 1][1], ah[2], al[2]);
        pack_hilo(acc1[2 * j + 1][2], acc1[2 * j + 1][3], ah[3], al[3]);
        const int bk = j * 16 + bkb;
#pragma unroll
        for (int p = 0; p < 5; p++) {
            uint32_t bh0, bh1, bh2, bh3, bl0_, bl1_, bl2_, bl3_;
            uint32_t addr = s2u(&sW2h[(p * 16 + bn2) * ST2 + bk]);
            LDMX4(bh0, bh1, bh2, bh3, addr);
            addr = s2u(&sW2l[(p * 16 + bn2) * ST2 + bk]);
            LDMX4(bl0_, bl1_, bl2_, bl3_, addr);
            MMA16816(acc2[2 * p + 0], ah[0], ah[1], ah[2], ah[3], bh0, bh1);
            MMA16816(acc2[2 * p + 0], ah[0], ah[1], ah[2], ah[3], bl0_, bl1_);
            MMA16816(acc2[2 * p + 0], al[0], al[1], al[2], al[3], bh0, bh1);
            MMA16816(acc2[2 * p + 1], ah[0], ah[1], ah[2], ah[3], bh2, bh3);
            MMA16816(acc2[2 * p + 1], ah[0], ah[1], ah[2], ah[3], bl2_, bl3_);
            MMA16816(acc2[2 * p + 1], al[0], al[1], al[2], al[3], bh2, bh3);
        }
    }

    // ---- epilogue: store tr (no bias; b2 added in final_k) ----
    const int r0 = rowBase + wid * 16 + (lane >> 2);
#pragma unroll
    for (int t = 0; t < 10; t++) {
        int col = t * 8 + cpair;
        if (r0 < M)
            *(float2*)(C + (size_t)r0 * 80 + col) = make_float2(acc2[t][0], acc2[t][1]);
        if (r0 + 8 < M)
            *(float2*)(C + (size_t)(r0 + 8) * 80 + col) = make_float2(acc2[t][2], acc2[t][3]);
    }
}

// ---------------- fused layer-2 gather-mean + root + bias + log_softmax ----------------
__global__ void final_k(const float* __restrict__ b2, float* __restrict__ out) {
    int gt = blockIdx.x * blockDim.x + threadIdx.x;
    int n = gt >> 5;
    int lane = gt & 31;
    if (n >= NN) return;
    int start = g_rowstart[n];
    int deg = g_deg[n];
    int c = lane * 2;
    float2 acc = make_float2(0.f, 0.f);
    if (lane < 20) {
        int i = 0;
        for (; i + 1 < deg; i += 2) {
            int s0 = __ldg(g_csr + start + i);
            int s1 = __ldg(g_csr + start + i + 1);
            float2 v0 = *(const float2*)(g_tr + (size_t)s0 * 80 + c);
            float2 v1 = *(const float2*)(g_tr + (size_t)s1 * 80 + c);
            acc.x += v0.x + v1.x;
            acc.y += v0.y + v1.y;
        }
        if (i < deg) {
            int s0 = __ldg(g_csr + start + i);
            float2 v0 = *(const float2*)(g_tr + (size_t)s0 * 80 + c);
            acc.x += v0.x;
            acc.y += v0.y;
        }
    }
    float inv = 1.0f / fmaxf((float)deg, 1.0f);
    float e0 = -3.4e38f, e1 = -3.4e38f;
    if (lane < 20) {
        e0 = acc.x * inv + g_tr[(size_t)n * 80 + 40 + c] + b2[c];
        e1 = acc.y * inv + g_tr[(size_t)n * 80 + 41 + c] + b2[c + 1];
    }
    float m = fmaxf(e0, e1);
#pragma unroll
    for (int o = 16; o > 0; o >>= 1) m = fmaxf(m, __shfl_xor_sync(0xffffffffu, m, o));
    float s = (lane < 20) ? (expf(e0 - m) + expf(e1 - m)) : 0.f;
#pragma unroll
    for (int o = 16; o > 0; o >>= 1) s += __shfl_xor_sync(0xffffffffu, s, o);
    float lse = m + logf(s);
    if (lane < 20) {
        float2 o2;
        o2.x = e0 - lse;
        o2.y = e1 - lse;
        *(float2*)(out + (size_t)n * 40 + c) = o2;
    }
}

// ---------------- launch ----------------
extern "C" void kernel_launch(void* const* d_in, const int* in_sizes, int n_in,
                              void* d_out, int out_size) {
    const float* x   = (const float*)d_in[0];
    const void* ei   = d_in[1];
    const float* W1l = (const float*)d_in[2];
    const float* W1r = (const float*)d_in[3];
    const float* b1  = (const float*)d_in[4];
    const float* W2l = (const float*)d_in[5];
    const float* W2r = (const float*)d_in[6];
    const float* b2  = (const float*)d_in[7];
    float* out       = (float*)d_out;

    float *agg1, *tr;
    cudaGetSymbolAddress((void**)&agg1, g_agg1);
    cudaGetSymbolAddress((void**)&tr, g_tr);

    const int mtiles = (NN + 127) / 128; // 782
    const int SMEMB = 84480;
    cudaFuncSetAttribute(gemm_fused, cudaFuncAttributeMaxDynamicSharedMemorySize, SMEMB);

    probe_k<<<1, 32>>>((const int*)ei);
    setup_k<<<(NN + 255) / 256, 256>>>(W1l, W1r, W2l, W2r);
    convert_k<<<(NE + 255) / 256, 256>>>(ei);
    scan1_k<<<NB, 1024>>>();
    scan2_k<<<1, 128>>>();
    scan3_k<<<(NN + 255) / 256, 256>>>();
    fill_k<<<(NE + 255) / 256, 256>>>();
    agg1_k<<<(NN * 32 + 255) / 256, 256>>>(x);
    gemm_fused<<<mtiles, 256, SMEMB>>>(NN, agg1, x, b1, tr);
    final_k<<<(NN * 32 + 255) / 256, 256>>>(b2, out);
}

// round 12
// speedup vs baseline: 1.0837x; 1.0837x over previous
#include <cuda_runtime.h>
#include <cuda_bf16.h>
#include <math.h>
#include <stdint.h>

#define NN 100000
#define NE 1600000
#define NB 98  // ceil(NN/1024) scan blocks

// ---------------- scratch (static __device__, no allocation) ----------------
__device__ __align__(16) float g_agg1[(size_t)NN * 128]; // layer-1 neighbor means
__device__ __align__(16) float g_h[(size_t)NN * 128];    // layer-1 output (relu)
__device__ __align__(16) float g_tr[(size_t)NN * 80];    // [h@W2l | h@W2r] per node
// weights pre-transposed to [N][K] (K contiguous) and split into bf16 hi/lo
__device__ __align__(16) unsigned short g_w1h[128 * 256];
__device__ __align__(16) unsigned short g_w1lo[128 * 256];
__device__ __align__(16) unsigned short g_w2h[80 * 128];
__device__ __align__(16) unsigned short g_w2lo[80 * 128];
__device__ int g_src[NE];
__device__ int g_dst[NE];
__device__ int g_csr[NE];
__device__ int g_deg[NN];
__device__ int g_rowstart[NN];
__device__ int g_cursor[NN];
__device__ int g_scan[NN];
__device__ int g_bsum[NB];
__device__ int g_is64;

// ---------------- PTX helpers (sm_80-era, valid at compute_100) ----------------
static __device__ __forceinline__ uint32_t s2u(const void* p) {
    uint32_t a;
    asm("{ .reg .u64 t; cvta.to.shared.u64 t, %1; cvt.u32.u64 %0, t; }" : "=r"(a) : "l"(p));
    return a;
}
#define LDMX4(r0, r1, r2, r3, addr)                                             \
    asm volatile("ldmatrix.sync.aligned.m8n8.x4.shared.b16 {%0,%1,%2,%3}, [%4];" \
                 : "=r"(r0), "=r"(r1), "=r"(r2), "=r"(r3) : "r"(addr))
#define MMA16816(d, a0, a1, a2, a3, b0, b1)                                     \
    asm volatile("mma.sync.aligned.m16n8k16.row.col.f32.bf16.bf16.f32 "          \
                 "{%0,%1,%2,%3},{%4,%5,%6,%7},{%8,%9},{%0,%1,%2,%3};"            \
                 : "+f"((d)[0]), "+f"((d)[1]), "+f"((d)[2]), "+f"((d)[3])        \
                 : "r"(a0), "r"(a1), "r"(a2), "r"(a3), "r"(b0), "r"(b1))

// ---------------- probe edge_index dtype (one warp, parallel) ----------------
__global__ void probe_k(const int* __restrict__ ei32) {
    int lane = threadIdx.x;
    int bad = 0;
#pragma unroll
    for (int i = 0; i < 4; i++)
        if (ei32[2 * (lane + 32 * i) + 1] != 0) bad = 1;
    bad = __any_sync(0xffffffffu, bad);
    if (lane == 0) g_is64 = bad ? 0 : 1;
}

// ---------------- setup: zero int scratch + pack/split weights ----------------
static __device__ __forceinline__ void split1(float v, unsigned short& h, unsigned short& l) {
    uint32_t u = __float_as_uint(v);
    h = (unsigned short)(u >> 16);
    float hf = __uint_as_float(u & 0xFFFF0000u);
    l = __bfloat16_as_ushort(__float2bfloat16(v - hf));
}
__global__ void setup_k(const float* __restrict__ W1l, const float* __restrict__ W1r,
                        const float* __restrict__ W2l, const float* __restrict__ W2r) {
    int i = blockIdx.x * blockDim.x + threadIdx.x;
    if (i < NN) { g_deg[i] = 0; g_cursor[i] = 0; }
    if (i < 128 * 256) { // w1: n = i/256, k = i%256
        int n = i >> 8, k = i & 255;
        float v = (k < 128) ? W1l[k * 128 + n] : W1r[(k - 128) * 128 + n];
        split1(v, g_w1h[i], g_w1lo[i]);
    }
    if (i < 80 * 128) { // w2: n = i/128, k = i%128
        int n = i >> 7, k = i & 127;
        float v = (n < 40) ? W2l[k * 40 + n] : W2r[k * 40 + (n - 40)];
        split1(v, g_w2h[i], g_w2lo[i]);
    }
}

// ---------------- edge convert + degree histogram ----------------
__global__ void convert_k(const void* __restrict__ ei) {
    int e = blockIdx.x * blockDim.x + threadIdx.x;
    if (e >= NE) return;
    int src, dst;
    if (g_is64) {
        src = (int)((const long long*)ei)[e];
        dst = (int)((const long long*)ei)[(long long)NE + e];
    } else {
        src = ((const int*)ei)[e];
        dst = ((const int*)ei)[NE + e];
    }
    g_src[e] = src;
    g_dst[e] = dst;
    atomicAdd(&g_deg[dst], 1);
}

// ---------------- prefix scan ----------------
__global__ __launch_bounds__(1024) void scan1_k() {
    __shared__ int s[1024];
    int t = threadIdx.x;
    int i = blockIdx.x * 1024 + t;
    int v = (i < NN) ? g_deg[i] : 0;
    s[t] = v;
    __syncthreads();
#pragma unroll
    for (int off = 1; off < 1024; off <<= 1) {
        int a = (t >= off) ? s[t - off] : 0;
        __syncthreads();
        s[t] += a;
        __syncthreads();
    }
    if (i < NN) g_scan[i] = s[t];
    if (t == 1023) g_bsum[blockIdx.x] = s[t];
}
__global__ void scan2_k() { // parallel Hillis-Steele over NB block sums
    __shared__ int s[128];
    int t = threadIdx.x;
    s[t] = (t < NB) ? g_bsum[t] : 0;
    __syncthreads();
#pragma unroll
    for (int off = 1; off < 128; off <<= 1) {
        int a = (t >= off) ? s[t - off] : 0;
        __syncthreads();
        s[t] += a;
        __syncthreads();
    }
    if (t < NB) g_bsum[t] = s[t];
}
__global__ void scan3_k() {
    int i = blockIdx.x * blockDim.x + threadIdx.x;
    if (i >= NN) return;
    int b = i >> 10;
    int base = (b > 0) ? g_bsum[b - 1] : 0;
    g_rowstart[i] = base + g_scan[i] - g_deg[i];
}

// ---------------- CSR fill ----------------
__global__ void fill_k() {
    int e = blockIdx.x * blockDim.x + threadIdx.x;
    if (e >= NE) return;
    int d = g_dst[e];
    int pos = g_rowstart[d] + atomicAdd(&g_cursor[d], 1);
    g_csr[pos] = g_src[e];
}

// ---------------- layer-1 gather-mean (unroll 4) ----------------
__global__ void agg1_k(const float* __restrict__ x) {
    int gt = blockIdx.x * blockDim.x + threadIdx.x;
    int n = gt >> 5;
    int lane = gt & 31;
    if (n >= NN) return;
    int start = g_rowstart[n];
    int deg = g_deg[n];
    float4 acc = make_float4(0.f, 0.f, 0.f, 0.f);
    int i = 0;
    for (; i + 3 < deg; i += 4) {
        int s0 = __ldg(g_csr + start + i);
        int s1 = __ldg(g_csr + start + i + 1);
        int s2 = __ldg(g_csr + start + i + 2);
        int s3 = __ldg(g_csr + start + i + 3);
        float4 v0 = ((const float4*)(x + (size_t)s0 * 128))[lane];
        float4 v1 = ((const float4*)(x + (size_t)s1 * 128))[lane];
        float4 v2 = ((const float4*)(x + (size_t)s2 * 128))[lane];
        float4 v3 = ((const float4*)(x + (size_t)s3 * 128))[lane];
        acc.x += (v0.x + v1.x) + (v2.x + v3.x);
        acc.y += (v0.y + v1.y) + (v2.y + v3.y);
        acc.z += (v0.z + v1.z) + (v2.z + v3.z);
        acc.w += (v0.w + v1.w) + (v2.w + v3.w);
    }
    for (; i < deg; i++) {
        int s0 = __ldg(g_csr + start + i);
        float4 v0 = ((const float4*)(x + (size_t)s0 * 128))[lane];
        acc.x += v0.x; acc.y += v0.y; acc.z += v0.z; acc.w += v0.w;
    }
    float inv = 1.0f / fmaxf((float)deg, 1.0f);
    acc.x *= inv; acc.y *= inv; acc.z *= inv; acc.w *= inv;
    ((float4*)(g_agg1 + (size_t)n * 128))[lane] = acc;
}

// ---------------- mma.sync split-bf16 GEMM (proven R9 version, unchanged) ----------------
// C[M,N] = [A0 | A1](M x KT fp32, split at col 128, both lda=128) @ B(KT x N),
// B given as [N][KT] bf16 hi/lo. D += Ah*Bh + Ah*Bl + Al*Bh (fp32 accum).
template <int N, int KT, bool RELU>
__global__ __launch_bounds__(256) void gemm_mma(
    int M, const float* __restrict__ A0, const float* __restrict__ A1,
    const unsigned short* __restrict__ Bh, const unsigned short* __restrict__ Bl,
    const float* __restrict__ bias, float* __restrict__ C) {
    constexpr int NT8 = N / 8;
    constexpr int KC = KT / 32;
    constexpr int ST = 40;
    __shared__ unsigned short sAh[128 * ST], sAl[128 * ST];
    __shared__ unsigned short sBh[N * ST], sBl[N * ST];

    const int tid = threadIdx.x;
    const int wid = tid >> 5, lane = tid & 31;
    const int rowBase = blockIdx.x * 128;

    float acc[NT8][4];
#pragma unroll
    for (int t = 0; t < NT8; t++)
#pragma unroll
        for (int q = 0; q < 4; q++) acc[t][q] = 0.f;

    const int arow = tid >> 1;
    const int ach = (tid & 1) * 16;
    const int gr_a = rowBase + arow;

    for (int c = 0; c < KC; c++) {
        const int gk = c * 32;
        const float* Ap = (gk < 128) ? (A0 + (size_t)gr_a * 128 + gk + ach)
                                     : (A1 + (size_t)gr_a * 128 + (gk - 128) + ach);
#pragma unroll
        for (int i = 0; i < 4; i++) {
            float4 v = (gr_a < M) ? *(const float4*)(Ap + i * 4)
                                  : make_float4(0.f, 0.f, 0.f, 0.f);
            uint32_t ux = __float_as_uint(v.x), uy = __float_as_uint(v.y);
            uint32_t uz = __float_as_uint(v.z), uw = __float_as_uint(v.w);
            uint2 hv, lv;
            hv.x = (ux >> 16) | (uy & 0xFFFF0000u);
            hv.y = (uz >> 16) | (uw & 0xFFFF0000u);
            unsigned short l0 = __bfloat16_as_ushort(
                __float2bfloat16(v.x - __uint_as_float(ux & 0xFFFF0000u)));
            unsigned short l1 = __bfloat16_as_ushort(
                __float2bfloat16(v.y - __uint_as_float(uy & 0xFFFF0000u)));
            unsigned short l2 = __bfloat16_as_ushort(
                __float2bfloat16(v.z - __uint_as_float(uz & 0xFFFF0000u)));
            unsigned short l3 = __bfloat16_as_ushort(
                __float2bfloat16(v.w - __uint_as_float(uw & 0xFFFF0000u)));
            lv.x = (uint32_t)l0 | ((uint32_t)l1 << 16);
            lv.y = (uint32_t)l2 | ((uint32_t)l3 << 16);
            *(uint2*)&sAh[arow * ST + ach + i * 4] = hv;
            *(uint2*)&sAl[arow * ST + ach + i * 4] = lv;
        }
        for (int idx = tid; idx < N * 4; idx += 256) {
            int n = idx >> 2, q = idx & 3;
            *(uint4*)&sBh[n * ST + q * 8] = *(const uint4*)(Bh + (size_t)n * KT + gk + q * 8);
            *(uint4*)&sBl[n * ST + q * 8] = *(const uint4*)(Bl + (size_t)n * KT + gk + q * 8);
        }
        __syncthreads();
#pragma unroll
        for (int ks = 0; ks < 2; ks++) {
            const int kb = ks * 16;
            const int am = wid * 16 + (lane & 7) + ((lane >> 3) & 1) * 8;
            const int ak = kb + (lane >> 4) * 8;
            uint32_t ah0, ah1, ah2, ah3, al0, al1, al2, al3;
            {
                uint32_t addr = s2u(&sAh[am * ST + ak]);
                LDMX4(ah0, ah1, ah2, ah3, addr);
                addr = s2u(&sAl[am * ST + ak]);
                LDMX4(al0, al1, al2, al3, addr);
            }
            const int bn = (lane & 7) + (lane >> 4) * 8;
            const int bk = kb + ((lane >> 3) & 1) * 8;
#pragma unroll
            for (int p = 0; p < NT8 / 2; p++) {
                uint32_t bh0, bh1, bh2, bh3, bl0_, bl1_, bl2_, bl3_;
                uint32_t addr = s2u(&sBh[(p * 16 + bn) * ST + bk]);
                LDMX4(bh0, bh1, bh2, bh3, addr);
                addr = s2u(&sBl[(p * 16 + bn) * ST + bk]);
                LDMX4(bl0_, bl1_, bl2_, bl3_, addr);
                MMA16816(acc[2 * p + 0], ah0, ah1, ah2, ah3, bh0, bh1);
                MMA16816(acc[2 * p + 0], ah0, ah1, ah2, ah3, bl0_, bl1_);
                MMA16816(acc[2 * p + 0], al0, al1, al2, al3, bh0, bh1);
                MMA16816(acc[2 * p + 1], ah0, ah1, ah2, ah3, bh2, bh3);
                MMA16816(acc[2 * p + 1], ah0, ah1, ah2, ah3, bl2_, bl3_);
                MMA16816(acc[2 * p + 1], al0, al1, al2, al3, bh2, bh3);
            }
        }
        __syncthreads();
    }
    const int r0 = rowBase + wid * 16 + (lane >> 2);
    const int col0 = (lane & 3) * 2;
#pragma unroll
    for (int t = 0; t < NT8; t++) {
        int col = t * 8 + col0;
        float2 v0 = make_float2(acc[t][0], acc[t][1]);
        float2 v1 = make_float2(acc[t][2], acc[t][3]);
        if (RELU) {
            float b0v = __ldg(bias + col), b1v = __ldg(bias + col + 1);
            v0.x = fmaxf(v0.x + b0v, 0.f); v0.y = fmaxf(v0.y + b1v, 0.f);
            v1.x = fmaxf(v1.x + b0v, 0.f); v1.y = fmaxf(v1.y + b1v, 0.f);
        }
        if (r0 < M)     *(float2*)(C + (size_t)r0 * N + col) = v0;
        if (r0 + 8 < M) *(float2*)(C + (size_t)(r0 + 8) * N + col) = v1;
    }
}

// ---------------- fused layer-2 gather-mean + root + bias + log_softmax ----------------
__global__ void final_k(const float* __restrict__ b2, float* __restrict__ out) {
    int gt = blockIdx.x * blockDim.x + threadIdx.x;
    int n = gt >> 5;
    int lane = gt & 31;
    if (n >= NN) return;
    int start = g_rowstart[n];
    int deg = g_deg[n];
    int c = lane * 2;
    float2 acc = make_float2(0.f, 0.f);
    if (lane < 20) {
        int i = 0;
        for (; i + 1 < deg; i += 2) {
            int s0 = __ldg(g_csr + start + i);
            int s1 = __ldg(g_csr + start + i + 1);
            float2 v0 = *(const float2*)(g_tr + (size_t)s0 * 80 + c);
            float2 v1 = *(const float2*)(g_tr + (size_t)s1 * 80 + c);
            acc.x += v0.x + v1.x;
            acc.y += v0.y + v1.y;
        }
        if (i < deg) {
            int s0 = __ldg(g_csr + start + i);
            float2 v0 = *(const float2*)(g_tr + (size_t)s0 * 80 + c);
            acc.x += v0.x;
            acc.y += v0.y;
        }
    }
    float inv = 1.0f / fmaxf((float)deg, 1.0f);
    float e0 = -3.4e38f, e1 = -3.4e38f;
    if (lane < 20) {
        e0 = acc.x * inv + g_tr[(size_t)n * 80 + 40 + c] + b2[c];
        e1 = acc.y * inv + g_tr[(size_t)n * 80 + 41 + c] + b2[c + 1];
    }
    float m = fmaxf(e0, e1);
#pragma unroll
    for (int o = 16; o > 0; o >>= 1) m = fmaxf(m, __shfl_xor_sync(0xffffffffu, m, o));
    float s = (lane < 20) ? (expf(e0 - m) + expf(e1 - m)) : 0.f;
#pragma unroll
    for (int o = 16; o > 0; o >>= 1) s += __shfl_xor_sync(0xffffffffu, s, o);
    float lse = m + logf(s);
    if (lane < 20) {
        float2 o2;
        o2.x = e0 - lse;
        o2.y = e1 - lse;
        *(float2*)(out + (size_t)n * 40 + c) = o2;
    }
}

// ---------------- launch ----------------
extern "C" void kernel_launch(void* const* d_in, const int* in_sizes, int n_in,
                              void* d_out, int out_size) {
    const float* x   = (const float*)d_in[0];
    const void* ei   = d_in[1];
    const float* W1l = (const float*)d_in[2];
    const float* W1r = (const float*)d_in[3];
    const float* b1  = (const float*)d_in[4];
    const float* W2l = (const float*)d_in[5];
    const float* W2r = (const float*)d_in[6];
    const float* b2  = (const float*)d_in[7];
    float* out       = (float*)d_out;

    float *agg1, *h, *tr;
    unsigned short *w1h, *w1lo, *w2h, *w2lo;
    cudaGetSymbolAddress((void**)&agg1, g_agg1);
    cudaGetSymbolAddress((void**)&h, g_h);
    cudaGetSymbolAddress((void**)&tr, g_tr);
    cudaGetSymbolAddress((void**)&w1h, g_w1h);
    cudaGetSymbolAddress((void**)&w1lo, g_w1lo);
    cudaGetSymbolAddress((void**)&w2h, g_w2h);
    cudaGetSymbolAddress((void**)&w2lo, g_w2lo);

    const int mtiles = (NN + 127) / 128; // 782

    probe_k<<<1, 32>>>((const int*)ei);
    setup_k<<<(NN + 255) / 256, 256>>>(W1l, W1r, W2l, W2r);
    convert_k<<<(NE + 255) / 256, 256>>>(ei);
    scan1_k<<<NB, 1024>>>();
    scan2_k<<<1, 128>>>();
    scan3_k<<<(NN + 255) / 256, 256>>>();
    fill_k<<<(NE + 255) / 256, 256>>>();
    agg1_k<<<(NN * 32 + 255) / 256, 256>>>(x);
    gemm_mma<128, 256, true><<<mtiles, 256>>>(NN, agg1, x, w1h, w1lo, b1, h);
    gemm_mma<80, 128, false><<<mtiles, 256>>>(NN, h, h, w2h, w2lo, nullptr, tr);
    final_k<<<(NN * 32 + 255) / 256, 256>>>(b2, out);
}